// round 3
// baseline (speedup 1.0000x reference)
#include <cuda_runtime.h>

// DiceLoss: softmax over C=19 + per-class dice reduction.
// logits [8,19,512,512] f32; targets [8,512,512] int32 (JAX x64-disabled
// downcasts the reference's "int64" to int32 on device).

#define CC      19
#define LOG_HW  18
#define HW      (1 << LOG_HW)       // 512*512
#define BATCH   8
#define NPIX    (BATCH * HW)        // 2,097,152
#define THREADS 256
#define NBLOCKS (NPIX / 4 / THREADS) // 2048 (each thread handles 4 pixels)
#define IGN     255

__device__ float g_ps[CC];   // per-class sum of probs over valid pixels
__device__ float g_in[CC];   // per-class intersection
__device__ float g_ct[CC];   // per-class valid-pixel counts

__global__ void zero_k() {
    int i = threadIdx.x;
    if (i < CC) { g_ps[i] = 0.f; g_in[i] = 0.f; g_ct[i] = 0.f; }
}

__global__ void __launch_bounds__(THREADS) dice_main(
    const float* __restrict__ logits, const int* __restrict__ targets)
{
    __shared__ float s_ps[CC], s_in[CC], s_ct[CC];
    const int tid = threadIdx.x;
    if (tid < CC) { s_ps[tid] = 0.f; s_in[tid] = 0.f; s_ct[tid] = 0.f; }
    __syncthreads();

    const int g  = blockIdx.x * THREADS + tid;   // group id
    const int p  = g << 2;                       // first pixel of group
    const int b  = p >> LOG_HW;                  // batch index (no group crosses b)
    const int hw = p & (HW - 1);
    const float* base = logits + (((size_t)b * CC) << LOG_HW) + hw;

    // ---- targets: 4 consecutive int32, one LDG.128 ----
    int4 t4 = *(const int4*)(targets + p);
    int t0 = t4.x, t1 = t4.y, t2 = t4.z, t3 = t4.w;
    float v0 = (t0 == IGN) ? 0.f : 1.f;
    float v1 = (t1 == IGN) ? 0.f : 1.f;
    float v2 = (t2 == IGN) ? 0.f : 1.f;
    float v3 = (t3 == IGN) ? 0.f : 1.f;
    // clamp defensively: invalid -> 0, and never index OOB even on bad data
    t0 = (t0 == IGN || (unsigned)t0 >= CC) ? 0 : t0;
    t1 = (t1 == IGN || (unsigned)t1 >= CC) ? 0 : t1;
    t2 = (t2 == IGN || (unsigned)t2 >= CC) ? 0 : t2;
    t3 = (t3 == IGN || (unsigned)t3 >= CC) ? 0 : t3;

    // ---- pass over classes: exp, denom, gather exp at true class ----
    float4 e[CC];
    float dx = 0.f, dy = 0.f, dz = 0.f, dw = 0.f;
    float ge0 = 0.f, ge1 = 0.f, ge2 = 0.f, ge3 = 0.f;
    #pragma unroll
    for (int c = 0; c < CC; c++) {
        float4 x = *(const float4*)(base + ((size_t)c << LOG_HW));
        float4 ee;
        ee.x = __expf(x.x); ee.y = __expf(x.y);
        ee.z = __expf(x.z); ee.w = __expf(x.w);
        dx += ee.x; dy += ee.y; dz += ee.z; dw += ee.w;
        if (c == t0) ge0 = ee.x;
        if (c == t1) ge1 = ee.y;
        if (c == t2) ge2 = ee.z;
        if (c == t3) ge3 = ee.w;
        e[c] = ee;
    }
    // validity folded into the reciprocal: invalid pixel contributes exactly 0
    const float rx = v0 * __fdividef(1.f, dx);
    const float ry = v1 * __fdividef(1.f, dy);
    const float rz = v2 * __fdividef(1.f, dz);
    const float rw = v3 * __fdividef(1.f, dw);

    // ---- intersection / counts: data-dependent scatter -> shared atomics ----
    atomicAdd(&s_in[t0], ge0 * rx);
    atomicAdd(&s_in[t1], ge1 * ry);
    atomicAdd(&s_in[t2], ge2 * rz);
    atomicAdd(&s_in[t3], ge3 * rw);
    atomicAdd(&s_ct[t0], v0);
    atomicAdd(&s_ct[t1], v1);
    atomicAdd(&s_ct[t2], v2);
    atomicAdd(&s_ct[t3], v3);

    // ---- probs_sum: per-class FFMA chain -> warp butterfly -> shared ----
    #pragma unroll
    for (int c = 0; c < CC; c++) {
        float a = e[c].x * rx + e[c].y * ry + e[c].z * rz + e[c].w * rw;
        #pragma unroll
        for (int o = 16; o > 0; o >>= 1)
            a += __shfl_xor_sync(0xffffffffu, a, o);
        if ((tid & 31) == 0) atomicAdd(&s_ps[c], a);
    }
    __syncthreads();

    if (tid < CC) {
        atomicAdd(&g_ps[tid], s_ps[tid]);
        atomicAdd(&g_in[tid], s_in[tid]);
        atomicAdd(&g_ct[tid], s_ct[tid]);
    }
}

__global__ void final_k(float* out) {
    int c = threadIdx.x;
    float l = 0.f, cnt = 0.f;
    if (c < CC) {
        float U    = g_ps[c] + g_ct[c];
        float dice = (2.f * g_in[c] + 1.f) / (U + 1.f);
        l   = 1.f - dice;
        cnt = g_ct[c];
    }
    #pragma unroll
    for (int o = 16; o > 0; o >>= 1) {
        l   += __shfl_xor_sync(0xffffffffu, l, o);
        cnt += __shfl_xor_sync(0xffffffffu, cnt, o);
    }
    if (c == 0) out[0] = (cnt > 0.f) ? l * (1.f / CC) : 0.f;
}

extern "C" void kernel_launch(void* const* d_in, const int* in_sizes, int n_in,
                              void* d_out, int out_size) {
    const float* logits  = (const float*)d_in[0];
    const int*   targets = (const int*)d_in[1];
    float*       out     = (float*)d_out;

    zero_k<<<1, 32>>>();
    dice_main<<<NBLOCKS, THREADS>>>(logits, targets);
    final_k<<<1, 32>>>(out);
}